// round 1
// baseline (speedup 1.0000x reference)
#include <cuda_runtime.h>
#include <cstdint>

#define NNODES 100000
#define IN_F   165
#define HID    128

// Scratch (allocation-free rule: __device__ globals)
__device__ float g_bufG[(size_t)NNODES * HID];   // (x@W)*dinv
__device__ float g_bufAgg[(size_t)NNODES * HID]; // edge-sum accumulator
__device__ float g_bufH[(size_t)NNODES * HID];   // layer activation
__device__ int   g_deg[NNODES];
__device__ float g_dinv[NNODES];

// ---------------- utility kernels ----------------

__global__ void zero_f4_kernel(float4* __restrict__ p, int n4) {
    int i = blockIdx.x * blockDim.x + threadIdx.x;
    if (i < n4) p[i] = make_float4(0.f, 0.f, 0.f, 0.f);
}

__global__ void zero_int_kernel(int* __restrict__ p, int n) {
    int i = blockIdx.x * blockDim.x + threadIdx.x;
    if (i < n) p[i] = 0;
}

__global__ void deg_kernel(const int* __restrict__ dst, int* __restrict__ deg, int e) {
    int i = blockIdx.x * blockDim.x + threadIdx.x;
    if (i < e) atomicAdd(&deg[dst[i]], 1);
}

__global__ void dinv_kernel(const int* __restrict__ deg, float* __restrict__ dinv, int n) {
    int i = blockIdx.x * blockDim.x + threadIdx.x;
    if (i < n) dinv[i] = rsqrtf((float)(deg[i] + 1));  // +1 self-loop; always > 0
}

// ---------------- GEMM: C[n,128] = A[n,K] @ W[K,128], rows scaled by dinv ----------------
// 64x128 tile, BK=16, 256 threads, each thread computes 8x4.

template <int K>
__global__ __launch_bounds__(256)
void gemm_rowscale_kernel(const float* __restrict__ A, const float* __restrict__ W,
                          const float* __restrict__ dinv, float* __restrict__ C, int n) {
    constexpr int BM = 64, BN = 128, BK = 16;
    __shared__ float As[BK][BM];
    __shared__ float Bs[BK][BN];

    const int tid  = threadIdx.x;
    const int trow = tid >> 5;   // 0..7   (8 row-groups of 8)
    const int tcol = tid & 31;   // 0..31  (32 col-groups of 4)
    const int rowBase = blockIdx.x * BM;

    float acc[8][4];
#pragma unroll
    for (int i = 0; i < 8; i++)
#pragma unroll
        for (int j = 0; j < 4; j++) acc[i][j] = 0.f;

    for (int k0 = 0; k0 < K; k0 += BK) {
        // load A tile (64 x 16): 1024 elems / 256 thr = 4 each
#pragma unroll
        for (int j = 0; j < 4; j++) {
            int i  = tid * 4 + j;
            int r  = i >> 4;
            int kk = i & 15;
            int gr = rowBase + r;
            int gk = k0 + kk;
            float v = 0.f;
            if (gr < n && gk < K) v = A[(size_t)gr * K + gk];
            As[kk][r] = v;
        }
        // load W tile (16 x 128): 2048 elems / 256 thr = 8 each (coalesced over n)
#pragma unroll
        for (int j = 0; j < 8; j++) {
            int i  = tid * 8 + j;
            int kk = i >> 7;
            int nn = i & 127;
            int gk = k0 + kk;
            Bs[kk][nn] = (gk < K) ? W[gk * BN + nn] : 0.f;
        }
        __syncthreads();

#pragma unroll
        for (int kk = 0; kk < BK; kk++) {
            float4 a0 = *(const float4*)&As[kk][trow * 8];
            float4 a1 = *(const float4*)&As[kk][trow * 8 + 4];
            float4 b  = *(const float4*)&Bs[kk][tcol * 4];
            float ar[8] = {a0.x, a0.y, a0.z, a0.w, a1.x, a1.y, a1.z, a1.w};
            float br[4] = {b.x, b.y, b.z, b.w};
#pragma unroll
            for (int i = 0; i < 8; i++)
#pragma unroll
                for (int j = 0; j < 4; j++) acc[i][j] += ar[i] * br[j];
        }
        __syncthreads();
    }

#pragma unroll
    for (int i = 0; i < 8; i++) {
        int r = rowBase + trow * 8 + i;
        if (r < n) {
            float s = dinv[r];
            float4 o = make_float4(acc[i][0] * s, acc[i][1] * s, acc[i][2] * s, acc[i][3] * s);
            *(float4*)&C[(size_t)r * BN + tcol * 4] = o;
        }
    }
}

// ---------------- edge aggregation: agg[dst] += g[src] (128 floats/edge, warp per edge) --------

__global__ void agg_kernel(const float4* __restrict__ g, float4* __restrict__ agg,
                           const int* __restrict__ src, const int* __restrict__ dst, int e) {
    int warp = (blockIdx.x * blockDim.x + threadIdx.x) >> 5;
    int lane = threadIdx.x & 31;
    if (warp >= e) return;
    int s = __ldg(&src[warp]);
    int d = __ldg(&dst[warp]);
    float4 v = g[(size_t)s * 32 + lane];
    float* p = (float*)&agg[(size_t)d * 32 + lane];
    asm volatile("red.global.add.v4.f32 [%0], {%1,%2,%3,%4};"
                 :: "l"(p), "f"(v.x), "f"(v.y), "f"(v.z), "f"(v.w)
                 : "memory");
}

// ---------------- epilogue: h = relu(dinv*(agg + g) + b) ----------------

__global__ void post_relu_kernel(const float4* __restrict__ g, const float4* __restrict__ agg,
                                 const float* __restrict__ dinv, const float4* __restrict__ b,
                                 float4* __restrict__ h, int n) {
    int idx = blockIdx.x * blockDim.x + threadIdx.x;  // over n*32 float4
    if (idx >= n * 32) return;
    int row = idx >> 5;
    int c4  = idx & 31;
    float s  = dinv[row];
    float4 gv = g[idx];
    float4 av = agg[idx];
    float4 bv = b[c4];
    float4 o;
    o.x = fmaxf(fmaf(s, av.x + gv.x, bv.x), 0.f);
    o.y = fmaxf(fmaf(s, av.y + gv.y, bv.y), 0.f);
    o.z = fmaxf(fmaf(s, av.z + gv.z, bv.z), 0.f);
    o.w = fmaxf(fmaf(s, av.w + gv.w, bv.w), 0.f);
    h[idx] = o;
}

// ---------------- classifier: out[n,2] = h @ Wc + bc (warp per node) ----------------

__global__ void classifier_kernel(const float4* __restrict__ h, const float* __restrict__ Wc,
                                  const float* __restrict__ bc, float* __restrict__ out, int n) {
    int warp = (blockIdx.x * blockDim.x + threadIdx.x) >> 5;
    int lane = threadIdx.x & 31;
    if (warp >= n) return;
    float4 v = h[(size_t)warp * 32 + lane];
    float hv[4] = {v.x, v.y, v.z, v.w};
    float p0 = 0.f, p1 = 0.f;
#pragma unroll
    for (int j = 0; j < 4; j++) {
        int k = lane * 4 + j;
        p0 = fmaf(hv[j], __ldg(&Wc[k * 2 + 0]), p0);
        p1 = fmaf(hv[j], __ldg(&Wc[k * 2 + 1]), p1);
    }
#pragma unroll
    for (int off = 16; off; off >>= 1) {
        p0 += __shfl_xor_sync(0xFFFFFFFFu, p0, off);
        p1 += __shfl_xor_sync(0xFFFFFFFFu, p1, off);
    }
    if (lane == 0) {
        out[(size_t)warp * 2 + 0] = p0 + bc[0];
        out[(size_t)warp * 2 + 1] = p1 + bc[1];
    }
}

// ---------------- launch ----------------

extern "C" void kernel_launch(void* const* d_in, const int* in_sizes, int n_in,
                              void* d_out, int out_size) {
    const float* x  = (const float*)d_in[0];
    const int*   ei = (const int*)d_in[1];
    const float* W1 = (const float*)d_in[2];
    const float* b1 = (const float*)d_in[3];
    const float* W2 = (const float*)d_in[4];
    const float* b2 = (const float*)d_in[5];
    const float* Wc = (const float*)d_in[6];
    const float* bc = (const float*)d_in[7];
    float* out = (float*)d_out;

    const int n = NNODES;
    const int e = in_sizes[1] / 2;
    const int* src = ei;
    const int* dst = ei + e;

    float *G, *AGG, *H, *DINV;
    int* DEG;
    cudaGetSymbolAddress((void**)&G,    g_bufG);
    cudaGetSymbolAddress((void**)&AGG,  g_bufAgg);
    cudaGetSymbolAddress((void**)&H,    g_bufH);
    cudaGetSymbolAddress((void**)&DINV, g_dinv);
    cudaGetSymbolAddress((void**)&DEG,  g_deg);

    const int n4       = n * (HID / 4);                 // 3.2M float4
    const int zB       = (n4 + 255) / 256;
    const int gemmB    = (n + 63) / 64;
    const int aggB     = (int)(((long long)e * 32 + 255) / 256);
    const int warpB    = (int)(((long long)n * 32 + 255) / 256);

    // degrees + dinv (shared by both layers)
    zero_int_kernel<<<(n + 255) / 256, 256>>>(DEG, n);
    deg_kernel<<<(e + 255) / 256, 256>>>(dst, DEG, e);
    dinv_kernel<<<(n + 255) / 256, 256>>>(DEG, DINV, n);

    // ---- layer 1 ----
    gemm_rowscale_kernel<IN_F><<<gemmB, 256>>>(x, W1, DINV, G, n);
    zero_f4_kernel<<<zB, 256>>>((float4*)AGG, n4);
    agg_kernel<<<aggB, 256>>>((const float4*)G, (float4*)AGG, src, dst, e);
    post_relu_kernel<<<zB, 256>>>((const float4*)G, (const float4*)AGG, DINV,
                                  (const float4*)b1, (float4*)H, n);

    // ---- layer 2 ----
    gemm_rowscale_kernel<HID><<<gemmB, 256>>>(H, W2, DINV, G, n);
    zero_f4_kernel<<<zB, 256>>>((float4*)AGG, n4);
    agg_kernel<<<aggB, 256>>>((const float4*)G, (float4*)AGG, src, dst, e);
    post_relu_kernel<<<zB, 256>>>((const float4*)G, (const float4*)AGG, DINV,
                                  (const float4*)b2, (float4*)H, n);

    // ---- classifier ----
    classifier_kernel<<<warpB, 256>>>((const float4*)H, Wc, bc, out, n);
}

// round 2
// speedup vs baseline: 1.6107x; 1.6107x over previous
#include <cuda_runtime.h>
#include <cstdint>

#define NNODES 100000
#define IN_F   165
#define HID    128

// Scratch (allocation-free rule: __device__ globals)
__device__ float g_bufG[(size_t)NNODES * HID];   // (x@W)*dinv
__device__ float g_bufAgg[(size_t)NNODES * HID]; // edge-sum accumulator (seeded with G)
__device__ float g_bufH[(size_t)NNODES * HID];   // layer activation
__device__ int   g_deg[NNODES];
__device__ float g_dinv[NNODES];

// ---------------- utility kernels ----------------

__global__ void zero_int_kernel(int* __restrict__ p, int n) {
    int i = blockIdx.x * blockDim.x + threadIdx.x;
    if (i < n) p[i] = 0;
}

__global__ void deg_kernel(const int* __restrict__ dst, int* __restrict__ deg, int e) {
    int i = blockIdx.x * blockDim.x + threadIdx.x;
    if (i < e) atomicAdd(&deg[dst[i]], 1);
}

__global__ void dinv_kernel(const int* __restrict__ deg, float* __restrict__ dinv, int n) {
    int i = blockIdx.x * blockDim.x + threadIdx.x;
    if (i < n) dinv[i] = rsqrtf((float)(deg[i] + 1));  // +1 self-loop; always > 0
}

// ---------------- GEMM: G[n,128] = (A[n,K] @ W[K,128]) * dinv[row]; AGG := G ----------------
// 128x128 block tile, BK=16, 256 threads (16x16), 8x8 per thread, smem double-buffered.

template <int K>
__global__ __launch_bounds__(256)
void gemm_rowscale_kernel(const float* __restrict__ A, const float* __restrict__ W,
                          const float* __restrict__ dinv,
                          float* __restrict__ G, float* __restrict__ AGG, int n) {
    constexpr int BM = 128, BN = 128, BK = 16;
    constexpr int APAD = 4;                      // keep 16B alignment for LDS.128
    constexpr int TILES = (K + BK - 1) / BK;

    __shared__ float As[2][BK][BM + APAD];
    __shared__ float Bs[2][BK][BN];

    const int tid = threadIdx.x;
    const int tx  = tid & 15;    // 0..15 col group (8 cols each)
    const int ty  = tid >> 4;    // 0..15 row group (8 rows each)
    const int rowBase = blockIdx.x * BM;

    float acc[8][8];
#pragma unroll
    for (int i = 0; i < 8; i++)
#pragma unroll
        for (int j = 0; j < 8; j++) acc[i][j] = 0.f;

    // prologue: load tile 0
    {
        const int k0 = 0;
#pragma unroll
        for (int j = 0; j < 8; j++) {
            int l = tid + 256 * j;
            int r = l >> 4, kk = l & 15;
            int gr = rowBase + r, gk = k0 + kk;
            float v = 0.f;
            if (gr < n && gk < K) v = A[(size_t)gr * K + gk];
            As[0][kk][r] = v;
        }
#pragma unroll
        for (int j = 0; j < 8; j++) {
            int l = tid + 256 * j;
            int kk = l >> 7, nn = l & 127;
            int gk = k0 + kk;
            Bs[0][kk][nn] = (gk < K) ? W[gk * BN + nn] : 0.f;
        }
    }
    __syncthreads();

    for (int t = 0; t < TILES; t++) {
        const int cur = t & 1;
        if (t + 1 < TILES) {
            const int k0 = (t + 1) * BK;
            const int nxt = cur ^ 1;
#pragma unroll
            for (int j = 0; j < 8; j++) {
                int l = tid + 256 * j;
                int r = l >> 4, kk = l & 15;
                int gr = rowBase + r, gk = k0 + kk;
                float v = 0.f;
                if (gr < n && gk < K) v = A[(size_t)gr * K + gk];
                As[nxt][kk][r] = v;
            }
#pragma unroll
            for (int j = 0; j < 8; j++) {
                int l = tid + 256 * j;
                int kk = l >> 7, nn = l & 127;
                int gk = k0 + kk;
                Bs[nxt][kk][nn] = (gk < K) ? W[gk * BN + nn] : 0.f;
            }
        }

#pragma unroll
        for (int kk = 0; kk < BK; kk++) {
            float4 a0 = *(const float4*)&As[cur][kk][ty * 8];
            float4 a1 = *(const float4*)&As[cur][kk][ty * 8 + 4];
            float4 b0 = *(const float4*)&Bs[cur][kk][tx * 8];
            float4 b1 = *(const float4*)&Bs[cur][kk][tx * 8 + 4];
            float ar[8] = {a0.x, a0.y, a0.z, a0.w, a1.x, a1.y, a1.z, a1.w};
            float br[8] = {b0.x, b0.y, b0.z, b0.w, b1.x, b1.y, b1.z, b1.w};
#pragma unroll
            for (int i = 0; i < 8; i++)
#pragma unroll
                for (int j = 0; j < 8; j++) acc[i][j] = fmaf(ar[i], br[j], acc[i][j]);
        }
        __syncthreads();
    }

    // epilogue: scale by dinv[row], write G and seed AGG with the same value (self-loop)
#pragma unroll
    for (int i = 0; i < 8; i++) {
        int r = rowBase + ty * 8 + i;
        if (r < n) {
            float s = dinv[r];
            float4 o0 = make_float4(acc[i][0] * s, acc[i][1] * s, acc[i][2] * s, acc[i][3] * s);
            float4 o1 = make_float4(acc[i][4] * s, acc[i][5] * s, acc[i][6] * s, acc[i][7] * s);
            size_t base = (size_t)r * BN + tx * 8;
            *(float4*)&G[base]       = o0;
            *(float4*)&G[base + 4]   = o1;
            *(float4*)&AGG[base]     = o0;
            *(float4*)&AGG[base + 4] = o1;
        }
    }
}

// ---------------- edge aggregation: agg[dst] += g[src] (128 floats/edge, warp per edge) --------

__global__ void agg_kernel(const float4* __restrict__ g, float4* __restrict__ agg,
                           const int* __restrict__ src, const int* __restrict__ dst, int e) {
    int warp = (blockIdx.x * blockDim.x + threadIdx.x) >> 5;
    int lane = threadIdx.x & 31;
    if (warp >= e) return;
    int s = __ldg(&src[warp]);
    int d = __ldg(&dst[warp]);
    float4 v = g[(size_t)s * 32 + lane];
    float* p = (float*)&agg[(size_t)d * 32 + lane];
    asm volatile("red.global.add.v4.f32 [%0], {%1,%2,%3,%4};"
                 :: "l"(p), "f"(v.x), "f"(v.y), "f"(v.z), "f"(v.w)
                 : "memory");
}

// ---------------- epilogue: h = relu(dinv*agg + b) ----------------

__global__ void post_relu_kernel(const float4* __restrict__ agg,
                                 const float* __restrict__ dinv, const float4* __restrict__ b,
                                 float4* __restrict__ h, int n) {
    int idx = blockIdx.x * blockDim.x + threadIdx.x;  // over n*32 float4
    if (idx >= n * 32) return;
    int row = idx >> 5;
    int c4  = idx & 31;
    float s  = dinv[row];
    float4 av = agg[idx];
    float4 bv = b[c4];
    float4 o;
    o.x = fmaxf(fmaf(s, av.x, bv.x), 0.f);
    o.y = fmaxf(fmaf(s, av.y, bv.y), 0.f);
    o.z = fmaxf(fmaf(s, av.z, bv.z), 0.f);
    o.w = fmaxf(fmaf(s, av.w, bv.w), 0.f);
    h[idx] = o;
}

// ---------------- classifier: out[n,2] = h @ Wc + bc (warp per node) ----------------

__global__ void classifier_kernel(const float4* __restrict__ h, const float* __restrict__ Wc,
                                  const float* __restrict__ bc, float* __restrict__ out, int n) {
    int warp = (blockIdx.x * blockDim.x + threadIdx.x) >> 5;
    int lane = threadIdx.x & 31;
    if (warp >= n) return;
    float4 v = h[(size_t)warp * 32 + lane];
    float hv[4] = {v.x, v.y, v.z, v.w};
    float p0 = 0.f, p1 = 0.f;
#pragma unroll
    for (int j = 0; j < 4; j++) {
        int k = lane * 4 + j;
        p0 = fmaf(hv[j], __ldg(&Wc[k * 2 + 0]), p0);
        p1 = fmaf(hv[j], __ldg(&Wc[k * 2 + 1]), p1);
    }
#pragma unroll
    for (int off = 16; off; off >>= 1) {
        p0 += __shfl_xor_sync(0xFFFFFFFFu, p0, off);
        p1 += __shfl_xor_sync(0xFFFFFFFFu, p1, off);
    }
    if (lane == 0) {
        out[(size_t)warp * 2 + 0] = p0 + bc[0];
        out[(size_t)warp * 2 + 1] = p1 + bc[1];
    }
}

// ---------------- launch ----------------

extern "C" void kernel_launch(void* const* d_in, const int* in_sizes, int n_in,
                              void* d_out, int out_size) {
    const float* x  = (const float*)d_in[0];
    const int*   ei = (const int*)d_in[1];
    const float* W1 = (const float*)d_in[2];
    const float* b1 = (const float*)d_in[3];
    const float* W2 = (const float*)d_in[4];
    const float* b2 = (const float*)d_in[5];
    const float* Wc = (const float*)d_in[6];
    const float* bc = (const float*)d_in[7];
    float* out = (float*)d_out;

    const int n = NNODES;
    const int e = in_sizes[1] / 2;
    const int* src = ei;
    const int* dst = ei + e;

    float *G, *AGG, *H, *DINV;
    int* DEG;
    cudaGetSymbolAddress((void**)&G,    g_bufG);
    cudaGetSymbolAddress((void**)&AGG,  g_bufAgg);
    cudaGetSymbolAddress((void**)&H,    g_bufH);
    cudaGetSymbolAddress((void**)&DINV, g_dinv);
    cudaGetSymbolAddress((void**)&DEG,  g_deg);

    const int n4    = n * (HID / 4);                 // 3.2M float4
    const int zB    = (n4 + 255) / 256;
    const int gemmB = (n + 127) / 128;
    const int aggB  = (int)(((long long)e * 32 + 255) / 256);
    const int clsB  = (int)(((long long)n * 32 + 255) / 256);

    // degrees + dinv (shared by both layers)
    zero_int_kernel<<<(n + 255) / 256, 256>>>(DEG, n);
    deg_kernel<<<(e + 255) / 256, 256>>>(dst, DEG, e);
    dinv_kernel<<<(n + 255) / 256, 256>>>(DEG, DINV, n);

    // ---- layer 1 ----
    gemm_rowscale_kernel<IN_F><<<gemmB, 256>>>(x, W1, DINV, G, AGG, n);
    agg_kernel<<<aggB, 256>>>((const float4*)G, (float4*)AGG, src, dst, e);
    post_relu_kernel<<<zB, 256>>>((const float4*)AGG, DINV, (const float4*)b1, (float4*)H, n);

    // ---- layer 2 ----
    gemm_rowscale_kernel<HID><<<gemmB, 256>>>(H, W2, DINV, G, AGG, n);
    agg_kernel<<<aggB, 256>>>((const float4*)G, (float4*)AGG, src, dst, e);
    post_relu_kernel<<<zB, 256>>>((const float4*)AGG, DINV, (const float4*)b2, (float4*)H, n);

    // ---- classifier ----
    classifier_kernel<<<clsB, 256>>>((const float4*)H, Wc, bc, out, n);
}

// round 3
// speedup vs baseline: 1.8909x; 1.1740x over previous
#include <cuda_runtime.h>
#include <cstdint>

#define NNODES 100000
#define EDGES  1600000
#define IN_F   165
#define HID    128

// Scratch (allocation-free rule: __device__ globals)
__device__ float g_bufG[(size_t)NNODES * HID];   // (x@W)*dinv
__device__ float g_bufH[(size_t)NNODES * HID];   // layer-1 activation
__device__ int   g_deg[NNODES];
__device__ float g_dinv[NNODES];
__device__ int   g_rowptr[NNODES];
__device__ int   g_cnt[NNODES];
__device__ int   g_csr_src[EDGES];
__device__ int   g_blockSums[128];

// ---------------- degree / dinv ----------------

__global__ void zero2_int_kernel(int* __restrict__ a, int* __restrict__ b, int n) {
    int i = blockIdx.x * blockDim.x + threadIdx.x;
    if (i < n) { a[i] = 0; b[i] = 0; }
}

__global__ void deg_kernel(const int* __restrict__ dst, int* __restrict__ deg, int e) {
    int i = blockIdx.x * blockDim.x + threadIdx.x;
    if (i < e) atomicAdd(&deg[dst[i]], 1);
}

__global__ void dinv_kernel(const int* __restrict__ deg, float* __restrict__ dinv, int n) {
    int i = blockIdx.x * blockDim.x + threadIdx.x;
    if (i < n) dinv[i] = rsqrtf((float)(deg[i] + 1));  // +1 self-loop; always > 0
}

// ---------------- exclusive prefix scan of deg -> rowptr (chunk = 2048/block) --------

__global__ __launch_bounds__(256)
void scan_block_sums(const int* __restrict__ deg, int* __restrict__ blockSums, int n) {
    __shared__ int sdata[256];
    int base = blockIdx.x * 2048;
    int tid = threadIdx.x;
    int s = 0;
#pragma unroll
    for (int j = 0; j < 8; j++) {
        int i = base + tid * 8 + j;
        if (i < n) s += deg[i];
    }
    sdata[tid] = s;
    __syncthreads();
    for (int off = 128; off; off >>= 1) {
        if (tid < off) sdata[tid] += sdata[tid + off];
        __syncthreads();
    }
    if (tid == 0) blockSums[blockIdx.x] = sdata[0];
}

__global__ void scan_offsets(int* __restrict__ blockSums, int nb) {
    if (threadIdx.x == 0 && blockIdx.x == 0) {
        int run = 0;
        for (int i = 0; i < nb; i++) { int v = blockSums[i]; blockSums[i] = run; run += v; }
    }
}

__global__ __launch_bounds__(256)
void scan_final(const int* __restrict__ deg, const int* __restrict__ blockSums,
                int* __restrict__ rowptr, int n) {
    __shared__ int tsum[256];
    int base = blockIdx.x * 2048;
    int tid = threadIdx.x;
    int loc[8];
    int s = 0;
#pragma unroll
    for (int j = 0; j < 8; j++) {
        int i = base + tid * 8 + j;
        int v = (i < n) ? deg[i] : 0;
        loc[j] = s;
        s += v;
    }
    tsum[tid] = s;
    __syncthreads();
    // inclusive Hillis-Steele over per-thread sums
    for (int off = 1; off < 256; off <<= 1) {
        int t = (tid >= off) ? tsum[tid - off] : 0;
        __syncthreads();
        tsum[tid] += t;
        __syncthreads();
    }
    int threadOff = tsum[tid] - s;  // exclusive
    int cOff = blockSums[blockIdx.x];
#pragma unroll
    for (int j = 0; j < 8; j++) {
        int i = base + tid * 8 + j;
        if (i < n) rowptr[i] = cOff + threadOff + loc[j];
    }
}

// ---------------- scatter edges into CSR slots ----------------

__global__ void scatter_kernel(const int* __restrict__ src, const int* __restrict__ dst,
                               const int* __restrict__ rowptr, int* __restrict__ cnt,
                               int* __restrict__ csr, int e) {
    int i = blockIdx.x * blockDim.x + threadIdx.x;
    if (i < e) {
        int d = dst[i];
        int pos = rowptr[d] + atomicAdd(&cnt[d], 1);
        csr[pos] = src[i];
    }
}

// ---------------- GEMM: G[n,128] = (A[n,K] @ W[K,128]) * dinv[row] ----------------
// 128x128 block tile, BK=16, 256 threads, 8x8 per thread, smem double-buffered.

template <int K>
__global__ __launch_bounds__(256)
void gemm_rowscale_kernel(const float* __restrict__ A, const float* __restrict__ W,
                          const float* __restrict__ dinv, float* __restrict__ G, int n) {
    constexpr int BM = 128, BN = 128, BK = 16;
    constexpr int APAD = 4;
    constexpr int TILES = (K + BK - 1) / BK;

    __shared__ float As[2][BK][BM + APAD];
    __shared__ float Bs[2][BK][BN];

    const int tid = threadIdx.x;
    const int tx  = tid & 15;
    const int ty  = tid >> 4;
    const int rowBase = blockIdx.x * BM;

    float acc[8][8];
#pragma unroll
    for (int i = 0; i < 8; i++)
#pragma unroll
        for (int j = 0; j < 8; j++) acc[i][j] = 0.f;

    // prologue: tile 0
    {
#pragma unroll
        for (int j = 0; j < 8; j++) {
            int l = tid + 256 * j;
            int r = l >> 4, kk = l & 15;
            int gr = rowBase + r, gk = kk;
            float v = 0.f;
            if (gr < n && gk < K) v = A[(size_t)gr * K + gk];
            As[0][kk][r] = v;
        }
#pragma unroll
        for (int j = 0; j < 8; j++) {
            int l = tid + 256 * j;
            int kk = l >> 7, nn = l & 127;
            Bs[0][kk][nn] = (kk < K) ? W[kk * BN + nn] : 0.f;
        }
    }
    __syncthreads();

    for (int t = 0; t < TILES; t++) {
        const int cur = t & 1;
        if (t + 1 < TILES) {
            const int k0 = (t + 1) * BK;
            const int nxt = cur ^ 1;
#pragma unroll
            for (int j = 0; j < 8; j++) {
                int l = tid + 256 * j;
                int r = l >> 4, kk = l & 15;
                int gr = rowBase + r, gk = k0 + kk;
                float v = 0.f;
                if (gr < n && gk < K) v = A[(size_t)gr * K + gk];
                As[nxt][kk][r] = v;
            }
#pragma unroll
            for (int j = 0; j < 8; j++) {
                int l = tid + 256 * j;
                int kk = l >> 7, nn = l & 127;
                int gk = k0 + kk;
                Bs[nxt][kk][nn] = (gk < K) ? W[gk * BN + nn] : 0.f;
            }
        }

#pragma unroll
        for (int kk = 0; kk < BK; kk++) {
            float4 a0 = *(const float4*)&As[cur][kk][ty * 8];
            float4 a1 = *(const float4*)&As[cur][kk][ty * 8 + 4];
            float4 b0 = *(const float4*)&Bs[cur][kk][tx * 8];
            float4 b1 = *(const float4*)&Bs[cur][kk][tx * 8 + 4];
            float ar[8] = {a0.x, a0.y, a0.z, a0.w, a1.x, a1.y, a1.z, a1.w};
            float br[8] = {b0.x, b0.y, b0.z, b0.w, b1.x, b1.y, b1.z, b1.w};
#pragma unroll
            for (int i = 0; i < 8; i++)
#pragma unroll
                for (int j = 0; j < 8; j++) acc[i][j] = fmaf(ar[i], br[j], acc[i][j]);
        }
        __syncthreads();
    }

#pragma unroll
    for (int i = 0; i < 8; i++) {
        int r = rowBase + ty * 8 + i;
        if (r < n) {
            float s = dinv[r];
            float4 o0 = make_float4(acc[i][0] * s, acc[i][1] * s, acc[i][2] * s, acc[i][3] * s);
            float4 o1 = make_float4(acc[i][4] * s, acc[i][5] * s, acc[i][6] * s, acc[i][7] * s);
            size_t base = (size_t)r * BN + tx * 8;
            *(float4*)&G[base]     = o0;
            *(float4*)&G[base + 4] = o1;
        }
    }
}

// ---------------- fused aggregation: warp per node, CSR segment, no atomics --------
// acc = g[self] + sum_{src in seg} g[src];  then either
//   FINAL=false: h = relu(dinv*acc + b) -> H
//   FINAL=true : h = relu(dinv*acc + b); out = h @ Wc + bc  (warp reduce)

template <bool FINAL>
__global__ __launch_bounds__(256)
void agg_fused_kernel(const float4* __restrict__ g, const int* __restrict__ csr,
                      const int* __restrict__ rowptr, const int* __restrict__ deg,
                      const float* __restrict__ dinv, const float4* __restrict__ bias,
                      float4* __restrict__ h,
                      const float4* __restrict__ Wc4, const float* __restrict__ bc,
                      float2* __restrict__ out, int n) {
    int node = (blockIdx.x * blockDim.x + threadIdx.x) >> 5;
    int lane = threadIdx.x & 31;
    if (node >= n) return;

    float4 a0 = g[(size_t)node * 32 + lane];  // self-loop term
    float4 a1 = make_float4(0.f, 0.f, 0.f, 0.f);
    float4 a2 = a1, a3 = a1;

    const int start = rowptr[node];
    const int cnt   = deg[node];
    int j = 0;
    for (; j + 4 <= cnt; j += 4) {
        int s0 = __ldg(&csr[start + j + 0]);
        int s1 = __ldg(&csr[start + j + 1]);
        int s2 = __ldg(&csr[start + j + 2]);
        int s3 = __ldg(&csr[start + j + 3]);
        float4 v0 = g[(size_t)s0 * 32 + lane];
        float4 v1 = g[(size_t)s1 * 32 + lane];
        float4 v2 = g[(size_t)s2 * 32 + lane];
        float4 v3 = g[(size_t)s3 * 32 + lane];
        a0.x += v0.x; a0.y += v0.y; a0.z += v0.z; a0.w += v0.w;
        a1.x += v1.x; a1.y += v1.y; a1.z += v1.z; a1.w += v1.w;
        a2.x += v2.x; a2.y += v2.y; a2.z += v2.z; a2.w += v2.w;
        a3.x += v3.x; a3.y += v3.y; a3.z += v3.z; a3.w += v3.w;
    }
    for (; j < cnt; j++) {
        int s0 = __ldg(&csr[start + j]);
        float4 v0 = g[(size_t)s0 * 32 + lane];
        a0.x += v0.x; a0.y += v0.y; a0.z += v0.z; a0.w += v0.w;
    }
    float4 acc;
    acc.x = (a0.x + a1.x) + (a2.x + a3.x);
    acc.y = (a0.y + a1.y) + (a2.y + a3.y);
    acc.z = (a0.z + a1.z) + (a2.z + a3.z);
    acc.w = (a0.w + a1.w) + (a2.w + a3.w);

    float s = dinv[node];
    float4 bv = bias[lane];
    float4 hv;
    hv.x = fmaxf(fmaf(s, acc.x, bv.x), 0.f);
    hv.y = fmaxf(fmaf(s, acc.y, bv.y), 0.f);
    hv.z = fmaxf(fmaf(s, acc.z, bv.z), 0.f);
    hv.w = fmaxf(fmaf(s, acc.w, bv.w), 0.f);

    if (!FINAL) {
        h[(size_t)node * 32 + lane] = hv;
    } else {
        // classifier: k = lane*4 + j; Wc row-major [128][2]
        float4 w0 = __ldg(&Wc4[lane * 2]);      // {Wc[k0][0],Wc[k0][1],Wc[k1][0],Wc[k1][1]}
        float4 w1 = __ldg(&Wc4[lane * 2 + 1]);  // {Wc[k2][0],Wc[k2][1],Wc[k3][0],Wc[k3][1]}
        float p0 = hv.x * w0.x + hv.y * w0.z + hv.z * w1.x + hv.w * w1.z;
        float p1 = hv.x * w0.y + hv.y * w0.w + hv.z * w1.y + hv.w * w1.w;
#pragma unroll
        for (int off = 16; off; off >>= 1) {
            p0 += __shfl_xor_sync(0xFFFFFFFFu, p0, off);
            p1 += __shfl_xor_sync(0xFFFFFFFFu, p1, off);
        }
        if (lane == 0) out[node] = make_float2(p0 + bc[0], p1 + bc[1]);
    }
}

// ---------------- launch ----------------

extern "C" void kernel_launch(void* const* d_in, const int* in_sizes, int n_in,
                              void* d_out, int out_size) {
    const float* x  = (const float*)d_in[0];
    const int*   ei = (const int*)d_in[1];
    const float* W1 = (const float*)d_in[2];
    const float* b1 = (const float*)d_in[3];
    const float* W2 = (const float*)d_in[4];
    const float* b2 = (const float*)d_in[5];
    const float* Wc = (const float*)d_in[6];
    const float* bc = (const float*)d_in[7];
    float* out = (float*)d_out;

    const int n = NNODES;
    const int e = in_sizes[1] / 2;
    const int* src = ei;
    const int* dst = ei + e;

    float *G, *H, *DINV;
    int *DEG, *ROWPTR, *CNT, *CSR, *BSUMS;
    cudaGetSymbolAddress((void**)&G,      g_bufG);
    cudaGetSymbolAddress((void**)&H,      g_bufH);
    cudaGetSymbolAddress((void**)&DINV,   g_dinv);
    cudaGetSymbolAddress((void**)&DEG,    g_deg);
    cudaGetSymbolAddress((void**)&ROWPTR, g_rowptr);
    cudaGetSymbolAddress((void**)&CNT,    g_cnt);
    cudaGetSymbolAddress((void**)&CSR,    g_csr_src);
    cudaGetSymbolAddress((void**)&BSUMS,  g_blockSums);

    const int gemmB  = (n + 127) / 128;
    const int aggB   = (int)(((long long)n * 32 + 255) / 256);
    const int scanB  = (n + 2047) / 2048;

    // ---- graph preprocessing (per-call; deterministic up to fp sum order) ----
    zero2_int_kernel<<<(n + 255) / 256, 256>>>(DEG, CNT, n);
    deg_kernel<<<(e + 255) / 256, 256>>>(dst, DEG, e);
    dinv_kernel<<<(n + 255) / 256, 256>>>(DEG, DINV, n);
    scan_block_sums<<<scanB, 256>>>(DEG, BSUMS, n);
    scan_offsets<<<1, 32>>>(BSUMS, scanB);
    scan_final<<<scanB, 256>>>(DEG, BSUMS, ROWPTR, n);
    scatter_kernel<<<(e + 255) / 256, 256>>>(src, dst, ROWPTR, CNT, CSR, e);

    // ---- layer 1 ----
    gemm_rowscale_kernel<IN_F><<<gemmB, 256>>>(x, W1, DINV, G, n);
    agg_fused_kernel<false><<<aggB, 256>>>((const float4*)G, CSR, ROWPTR, DEG, DINV,
                                           (const float4*)b1, (float4*)H,
                                           nullptr, nullptr, nullptr, n);

    // ---- layer 2 (+ fused classifier) ----
    gemm_rowscale_kernel<HID><<<gemmB, 256>>>(H, W2, DINV, G, n);
    agg_fused_kernel<true><<<aggB, 256>>>((const float4*)G, CSR, ROWPTR, DEG, DINV,
                                          (const float4*)b2, nullptr,
                                          (const float4*)Wc, bc, (float2*)out, n);
}

// round 4
// speedup vs baseline: 2.5989x; 1.3744x over previous
#include <cuda_runtime.h>
#include <cstdint>

#define NNODES 100000
#define EDGES  1600000
#define IN_F   165
#define HID    128

// Scratch (allocation-free rule: __device__ globals)
__device__ float g_bufG[(size_t)NNODES * HID];   // (x@W)*dinv
__device__ float g_bufH[(size_t)NNODES * HID];   // layer-1 activation
__device__ int   g_deg[NNODES];
__device__ float g_dinv[NNODES];
__device__ int   g_rowptr[NNODES + 1];
__device__ int   g_cnt[NNODES];
__device__ int   g_csr_src[EDGES];
__device__ int   g_blockSums[128];

// ---------------- degree ----------------

__global__ void zero2_int_kernel(int* __restrict__ a, int* __restrict__ b, int n) {
    int i = blockIdx.x * blockDim.x + threadIdx.x;
    if (i < n) { a[i] = 0; b[i] = 0; }
}

__global__ void deg_kernel(const int* __restrict__ dst, int* __restrict__ deg, int e) {
    int i = blockIdx.x * blockDim.x + threadIdx.x;
    if (i < e) atomicAdd(&deg[dst[i]], 1);
}

// ---------------- exclusive prefix scan of deg -> rowptr; also dinv ----------------

__global__ __launch_bounds__(256)
void scan_block_sums(const int* __restrict__ deg, int* __restrict__ blockSums, int n) {
    __shared__ int sdata[256];
    int base = blockIdx.x * 2048;
    int tid = threadIdx.x;
    int s = 0;
#pragma unroll
    for (int j = 0; j < 8; j++) {
        int i = base + tid * 8 + j;
        if (i < n) s += deg[i];
    }
    sdata[tid] = s;
    __syncthreads();
    for (int off = 128; off; off >>= 1) {
        if (tid < off) sdata[tid] += sdata[tid + off];
        __syncthreads();
    }
    if (tid == 0) blockSums[blockIdx.x] = sdata[0];
}

__global__ void scan_offsets(int* __restrict__ blockSums, int nb) {
    if (threadIdx.x == 0 && blockIdx.x == 0) {
        int run = 0;
        for (int i = 0; i < nb; i++) { int v = blockSums[i]; blockSums[i] = run; run += v; }
    }
}

__global__ __launch_bounds__(256)
void scan_final(const int* __restrict__ deg, const int* __restrict__ blockSums,
                int* __restrict__ rowptr, float* __restrict__ dinv, int n) {
    __shared__ int tsum[256];
    int base = blockIdx.x * 2048;
    int tid = threadIdx.x;
    int loc[8];
    int dv[8];
    int s = 0;
#pragma unroll
    for (int j = 0; j < 8; j++) {
        int i = base + tid * 8 + j;
        int v = (i < n) ? deg[i] : 0;
        dv[j]  = v;
        loc[j] = s;
        s += v;
    }
    tsum[tid] = s;
    __syncthreads();
    for (int off = 1; off < 256; off <<= 1) {
        int t = (tid >= off) ? tsum[tid - off] : 0;
        __syncthreads();
        tsum[tid] += t;
        __syncthreads();
    }
    int threadOff = tsum[tid] - s;  // exclusive within block
    int cOff = blockSums[blockIdx.x];
#pragma unroll
    for (int j = 0; j < 8; j++) {
        int i = base + tid * 8 + j;
        if (i < n) {
            int rp = cOff + threadOff + loc[j];
            rowptr[i] = rp;
            dinv[i]   = rsqrtf((float)(dv[j] + 1));   // +1 self-loop
            if (i == n - 1) rowptr[n] = rp + dv[j];
        }
    }
}

// ---------------- scatter edges into CSR slots ----------------

__global__ void scatter_kernel(const int* __restrict__ src, const int* __restrict__ dst,
                               const int* __restrict__ rowptr, int* __restrict__ cnt,
                               int* __restrict__ csr, int e) {
    int i = blockIdx.x * blockDim.x + threadIdx.x;
    if (i < e) {
        int d = dst[i];
        int pos = rowptr[d] + atomicAdd(&cnt[d], 1);
        csr[pos] = src[i];
    }
}

// ---------------- GEMM: G[n,128] = (A[n,K] @ W[K,128]) * dinv[row] ----------------
// 128x128 block tile, BK=16, 256 threads, 8x8 per thread, smem double-buffered.

template <int K>
__global__ __launch_bounds__(256)
void gemm_rowscale_kernel(const float* __restrict__ A, const float* __restrict__ W,
                          const float* __restrict__ dinv, float* __restrict__ G, int n) {
    constexpr int BM = 128, BN = 128, BK = 16;
    constexpr int APAD = 4;
    constexpr int TILES = (K + BK - 1) / BK;
    constexpr bool KV4 = (K % BK) == 0;   // vectorizable A loads (K=128)

    __shared__ float As[2][BK][BM + APAD];
    __shared__ float Bs[2][BK][BN];

    const int tid = threadIdx.x;
    const int tx  = tid & 15;
    const int ty  = tid >> 4;
    const int rowBase = blockIdx.x * BM;

    float acc[8][8];
#pragma unroll
    for (int i = 0; i < 8; i++)
#pragma unroll
        for (int j = 0; j < 8; j++) acc[i][j] = 0.f;

    auto loadA = [&](int k0, int buf) {
        if (KV4) {
            // 2048 floats = 512 float4; 2 per thread. q -> row = q>>2, kq = (q&3)*4
#pragma unroll
            for (int j = 0; j < 2; j++) {
                int q  = tid * 2 + j;
                int r  = q >> 2;
                int kq = (q & 3) * 4;
                int gr = rowBase + r;
                float4 v = make_float4(0.f, 0.f, 0.f, 0.f);
                if (gr < n) v = *(const float4*)&A[(size_t)gr * K + k0 + kq];
                As[buf][kq + 0][r] = v.x;
                As[buf][kq + 1][r] = v.y;
                As[buf][kq + 2][r] = v.z;
                As[buf][kq + 3][r] = v.w;
            }
        } else {
#pragma unroll
            for (int j = 0; j < 8; j++) {
                int l = tid + 256 * j;
                int r = l >> 4, kk = l & 15;
                int gr = rowBase + r, gk = k0 + kk;
                float v = 0.f;
                if (gr < n && gk < K) v = A[(size_t)gr * K + gk];
                As[buf][kk][r] = v;
            }
        }
    };
    auto loadB = [&](int k0, int buf) {
#pragma unroll
        for (int j = 0; j < 8; j++) {
            int l = tid + 256 * j;
            int kk = l >> 7, nn = l & 127;
            int gk = k0 + kk;
            Bs[buf][kk][nn] = (gk < K) ? W[gk * BN + nn] : 0.f;
        }
    };

    loadA(0, 0);
    loadB(0, 0);
    __syncthreads();

    for (int t = 0; t < TILES; t++) {
        const int cur = t & 1;
        if (t + 1 < TILES) {
            loadA((t + 1) * BK, cur ^ 1);
            loadB((t + 1) * BK, cur ^ 1);
        }

#pragma unroll
        for (int kk = 0; kk < BK; kk++) {
            float4 a0 = *(const float4*)&As[cur][kk][ty * 8];
            float4 a1 = *(const float4*)&As[cur][kk][ty * 8 + 4];
            float4 b0 = *(const float4*)&Bs[cur][kk][tx * 8];
            float4 b1 = *(const float4*)&Bs[cur][kk][tx * 8 + 4];
            float ar[8] = {a0.x, a0.y, a0.z, a0.w, a1.x, a1.y, a1.z, a1.w};
            float br[8] = {b0.x, b0.y, b0.z, b0.w, b1.x, b1.y, b1.z, b1.w};
#pragma unroll
            for (int i = 0; i < 8; i++)
#pragma unroll
                for (int j = 0; j < 8; j++) acc[i][j] = fmaf(ar[i], br[j], acc[i][j]);
        }
        __syncthreads();
    }

#pragma unroll
    for (int i = 0; i < 8; i++) {
        int r = rowBase + ty * 8 + i;
        if (r < n) {
            float s = dinv[r];
            float4 o0 = make_float4(acc[i][0] * s, acc[i][1] * s, acc[i][2] * s, acc[i][3] * s);
            float4 o1 = make_float4(acc[i][4] * s, acc[i][5] * s, acc[i][6] * s, acc[i][7] * s);
            size_t base = (size_t)r * BN + tx * 8;
            *(float4*)&G[base]     = o0;
            *(float4*)&G[base + 4] = o1;
        }
    }
}

// ---------------- fused aggregation: warp per node, CSR segment, no atomics --------
// acc = g[self] + sum_{src in seg} g[src];
//   FINAL=false: h = relu(dinv*acc + b) -> H
//   FINAL=true : h = relu(dinv*acc + b); out = h @ Wc + bc  (warp reduce)

template <bool FINAL>
__global__ __launch_bounds__(256)
void agg_fused_kernel(const float4* __restrict__ g, const int* __restrict__ csr,
                      const int* __restrict__ rowptr,
                      const float* __restrict__ dinv, const float4* __restrict__ bias,
                      float4* __restrict__ h,
                      const float4* __restrict__ Wc4, const float* __restrict__ bc,
                      float2* __restrict__ out, int n) {
    int node = (blockIdx.x * blockDim.x + threadIdx.x) >> 5;
    int lane = threadIdx.x & 31;
    if (node >= n) return;

    const int start = rowptr[node];
    const int end   = rowptr[node + 1];
    const int cnt   = end - start;

    float4 a[8];
    a[0] = g[(size_t)node * 32 + lane];  // self-loop term
#pragma unroll
    for (int i = 1; i < 8; i++) a[i] = make_float4(0.f, 0.f, 0.f, 0.f);

    int j = 0;
    for (; j + 8 <= cnt; j += 8) {
        int idx[8];
#pragma unroll
        for (int u = 0; u < 8; u++) idx[u] = __ldg(&csr[start + j + u]);
#pragma unroll
        for (int u = 0; u < 8; u++) {
            float4 v = g[(size_t)idx[u] * 32 + lane];
            a[u].x += v.x; a[u].y += v.y; a[u].z += v.z; a[u].w += v.w;
        }
    }
    if (j + 4 <= cnt) {
        int idx[4];
#pragma unroll
        for (int u = 0; u < 4; u++) idx[u] = __ldg(&csr[start + j + u]);
#pragma unroll
        for (int u = 0; u < 4; u++) {
            float4 v = g[(size_t)idx[u] * 32 + lane];
            a[u].x += v.x; a[u].y += v.y; a[u].z += v.z; a[u].w += v.w;
        }
        j += 4;
    }
    for (; j < cnt; j++) {
        int s0 = __ldg(&csr[start + j]);
        float4 v = g[(size_t)s0 * 32 + lane];
        a[0].x += v.x; a[0].y += v.y; a[0].z += v.z; a[0].w += v.w;
    }

    float4 acc;
    acc.x = ((a[0].x + a[1].x) + (a[2].x + a[3].x)) + ((a[4].x + a[5].x) + (a[6].x + a[7].x));
    acc.y = ((a[0].y + a[1].y) + (a[2].y + a[3].y)) + ((a[4].y + a[5].y) + (a[6].y + a[7].y));
    acc.z = ((a[0].z + a[1].z) + (a[2].z + a[3].z)) + ((a[4].z + a[5].z) + (a[6].z + a[7].z));
    acc.w = ((a[0].w + a[1].w) + (a[2].w + a[3].w)) + ((a[4].w + a[5].w) + (a[6].w + a[7].w));

    float s = dinv[node];
    float4 bv = bias[lane];
    float4 hv;
    hv.x = fmaxf(fmaf(s, acc.x, bv.x), 0.f);
    hv.y = fmaxf(fmaf(s, acc.y, bv.y), 0.f);
    hv.z = fmaxf(fmaf(s, acc.z, bv.z), 0.f);
    hv.w = fmaxf(fmaf(s, acc.w, bv.w), 0.f);

    if (!FINAL) {
        h[(size_t)node * 32 + lane] = hv;
    } else {
        float4 w0 = __ldg(&Wc4[lane * 2]);
        float4 w1 = __ldg(&Wc4[lane * 2 + 1]);
        float p0 = hv.x * w0.x + hv.y * w0.z + hv.z * w1.x + hv.w * w1.z;
        float p1 = hv.x * w0.y + hv.y * w0.w + hv.z * w1.y + hv.w * w1.w;
#pragma unroll
        for (int off = 16; off; off >>= 1) {
            p0 += __shfl_xor_sync(0xFFFFFFFFu, p0, off);
            p1 += __shfl_xor_sync(0xFFFFFFFFu, p1, off);
        }
        if (lane == 0) out[node] = make_float2(p0 + bc[0], p1 + bc[1]);
    }
}

// ---------------- launch ----------------

extern "C" void kernel_launch(void* const* d_in, const int* in_sizes, int n_in,
                              void* d_out, int out_size) {
    const float* x  = (const float*)d_in[0];
    const int*   ei = (const int*)d_in[1];
    const float* W1 = (const float*)d_in[2];
    const float* b1 = (const float*)d_in[3];
    const float* W2 = (const float*)d_in[4];
    const float* b2 = (const float*)d_in[5];
    const float* Wc = (const float*)d_in[6];
    const float* bc = (const float*)d_in[7];
    float* out = (float*)d_out;

    const int n = NNODES;
    const int e = in_sizes[1] / 2;
    const int* src = ei;
    const int* dst = ei + e;

    float *G, *H, *DINV;
    int *DEG, *ROWPTR, *CNT, *CSR, *BSUMS;
    cudaGetSymbolAddress((void**)&G,      g_bufG);
    cudaGetSymbolAddress((void**)&H,      g_bufH);
    cudaGetSymbolAddress((void**)&DINV,   g_dinv);
    cudaGetSymbolAddress((void**)&DEG,    g_deg);
    cudaGetSymbolAddress((void**)&ROWPTR, g_rowptr);
    cudaGetSymbolAddress((void**)&CNT,    g_cnt);
    cudaGetSymbolAddress((void**)&CSR,    g_csr_src);
    cudaGetSymbolAddress((void**)&BSUMS,  g_blockSums);

    const int gemmB = (n + 127) / 128;
    const int aggB  = (int)(((long long)n * 32 + 255) / 256);
    const int scanB = (n + 2047) / 2048;

    // ---- graph preprocessing ----
    zero2_int_kernel<<<(n + 255) / 256, 256>>>(DEG, CNT, n);
    deg_kernel<<<(e + 255) / 256, 256>>>(dst, DEG, e);
    scan_block_sums<<<scanB, 256>>>(DEG, BSUMS, n);
    scan_offsets<<<1, 32>>>(BSUMS, scanB);
    scan_final<<<scanB, 256>>>(DEG, BSUMS, ROWPTR, DINV, n);
    scatter_kernel<<<(e + 255) / 256, 256>>>(src, dst, ROWPTR, CNT, CSR, e);

    // ---- layer 1 ----
    gemm_rowscale_kernel<IN_F><<<gemmB, 256>>>(x, W1, DINV, G, n);
    agg_fused_kernel<false><<<aggB, 256>>>((const float4*)G, CSR, ROWPTR, DINV,
                                           (const float4*)b1, (float4*)H,
                                           nullptr, nullptr, nullptr, n);

    // ---- layer 2 (+ fused classifier) ----
    gemm_rowscale_kernel<HID><<<gemmB, 256>>>(H, W2, DINV, G, n);
    agg_fused_kernel<true><<<aggB, 256>>>((const float4*)G, CSR, ROWPTR, DINV,
                                          (const float4*)b2, nullptr,
                                          (const float4*)Wc, bc, (float2*)out, n);
}